// round 2
// baseline (speedup 1.0000x reference)
#include <cuda_runtime.h>
#include <cuda_bf16.h>
#include <math_constants.h>

// Problem constants (fixed by the reference)
#define BB     2
#define HH     112
#define WW     112
#define HW     (HH * WW)        // 12544
#define NPIX   (BB * HW)        // 25088
#define SEG_T  0.7f
#define EPS_K  1e-7f
// Output nonzero requires q <= eps - ln(0.7) = 0.3566750.
// Radius bound uses 0.36 (margin), store cutoff 0.37 (margin).
#define Q_RAD  0.36f
#define Q_CUT  0.37f

// Scratch: per-pixel running min of the quadratic q, stored as float bits.
// q >= 0 (PSD form), so unsigned ordering == float ordering and atomicMin on
// uint implements float-min. Fixed-size __device__ global: no allocation.
__device__ unsigned int g_qmin[NPIX];

// ---------------------------------------------------------------------------
// Kernel A: reset the min-field to +inf bits (graph replays need this fresh).
// ---------------------------------------------------------------------------
__global__ void k_init()
{
    int idx = blockIdx.x * blockDim.x + threadIdx.x;
    if (idx < NPIX) g_qmin[idx] = 0x7F800000u;   // +inf
}

// ---------------------------------------------------------------------------
// Kernel B: one thread per source pixel. If selected, compute the anisotropic
// gaussian's quadratic coefficients and atomicMin-scatter q into the pruned
// bounding box where q could be <= 0.3567 (min-eigenvalue radius bound).
// ---------------------------------------------------------------------------
__global__ void k_scatter(const float* __restrict__ variance,
                          const float* __restrict__ center)
{
    int idx = blockIdx.x * blockDim.x + threadIdx.x;
    if (idx >= NPIX) return;

    int b   = idx / HW;
    int pix = idx - b * HW;
    int pr  = pix / WW;     // row of this source point
    int pc  = pix - pr * WW;

    float cm   = center[idx];
    float mask = (cm > SEG_T) ? 1.0f : 0.0f;

    const float* varb = variance + (size_t)b * 3 * HW;
    float vx = varb[pix]      * mask;
    float vy = varb[HW + pix] * mask;
    // sel = (vx + vy) != 0  (matches torch.nonzero(vx+vy) semantics)
    if ((vx + vy) == 0.0f) return;

    float v2    = varb[2 * HW + pix];
    float theta = 3.14f * (1.0f / (1.0f + expf(-v2)));
    float s, c;
    sincosf(theta, &s, &c);

    float var_x = vx * vx + EPS_K;
    float var_y = vy * vy + EPS_K;

    float inv2x = 1.0f / (2.0f * var_x);
    float inv2y = 1.0f / (2.0f * var_y);

    // a = cos^2/(2vx) + sin^2/(2vy);  c = sin^2/(2vx) + cos^2/(2vy)
    float A  = c * c * inv2x + s * s * inv2y;
    float C  = s * s * inv2x + c * c * inv2y;
    // ref: b = -2sc/(4vx) + 2sc/(4vy); the form uses 2*b as cross coefficient
    float B2 = 2.0f * (-2.0f * s * c / (4.0f * var_x)
                       + 2.0f * s * c / (4.0f * var_y));

    // Pruning radius: q >= d^2 / (2*max(var_x,var_y)); q<=0.3567 requires
    // d^2 <= 2*maxvar*0.3567.  Use 0.36 + floor+1 for fp safety.
    float maxvar = fmaxf(var_x, var_y);
    int R = (int)floorf(sqrtf(2.0f * maxvar * Q_RAD)) + 1;

    int i0 = max(0, pr - R), i1 = min(HH - 1, pr + R);
    int j0 = max(0, pc - R), j1 = min(WW - 1, pc + R);

    unsigned int* qf = g_qmin + (size_t)b * HW;
    for (int i = i0; i <= i1; ++i) {
        float di  = (float)(i - pr);
        float adi = A * di * di;
        float bdi = B2 * di;
        for (int j = j0; j <= j1; ++j) {
            float dj = (float)(j - pc);
            float q  = fmaf(C * dj + bdi, dj, adi);  // adi + bdi*dj + C*dj*dj
            if (q <= Q_CUT) {
                atomicMin(&qf[i * WW + j], __float_as_uint(q));
            }
        }
    }
}

// ---------------------------------------------------------------------------
// Kernel C: per output element -> exp(-qmin + eps), threshold at 0.7.
// Also zero-fills any extra trailing output elements (the `flag` scalar).
// ---------------------------------------------------------------------------
__global__ void k_finalize(float* __restrict__ out, int out_size)
{
    int idx = blockIdx.x * blockDim.x + threadIdx.x;
    if (idx >= out_size) return;
    if (idx < NPIX) {
        float q = __uint_as_float(g_qmin[idx]);
        float g = expf(-q + EPS_K);          // q=+inf -> g=0
        out[idx] = (g >= 0.7f) ? g : 0.0f;
    } else {
        out[idx] = 0.0f;                      // flag = False
    }
}

// ---------------------------------------------------------------------------
// Inputs (metadata order): x[2,32,112,112], variance[2,3,112,112],
// center_map[2,1,112,112], conv_w[1,32], conv_b[1].
// x / conv_w / conv_b are dead in the reference (threshold branch unused).
// ---------------------------------------------------------------------------
extern "C" void kernel_launch(void* const* d_in, const int* in_sizes, int n_in,
                              void* d_out, int out_size)
{
    const float* variance = (const float*)d_in[1];
    const float* center   = (const float*)d_in[2];
    float*       out      = (float*)d_out;

    const int T = 256;
    k_init<<<(NPIX + T - 1) / T, T>>>();
    k_scatter<<<(NPIX + T - 1) / T, T>>>(variance, center);
    k_finalize<<<(out_size + T - 1) / T, T>>>(out, out_size);
}